// round 1
// baseline (speedup 1.0000x reference)
#include <cuda_runtime.h>
#include <cuda_bf16.h>
#include <math.h>

// Problem constants
#define BATCH   2
#define SEQ     2048
#define DMODEL  1024
#define NHEAD   16
#define DHEAD   64
#define BT      (BATCH * SEQ)          // 4096 rows

// Scratch (device globals; no allocation allowed)
__device__ float g_q[BT * DMODEL];     // 16 MB
__device__ float g_k[BT * DMODEL];     // 16 MB
__device__ float g_v[BT * DMODEL];     // 16 MB
__device__ float g_attn[BT * DMODEL];  // 16 MB

// ---------------------------------------------------------------------------
// 128x128x8 SGEMM tile, NT form: C[m,n] = sum_k A[m,k] * B[n,k]
// A: M x K row-major (lda=K), B: N x K row-major (ldb=K), C: M x N (ldc=N)
// 256 threads, each computes an 8x8 micro-tile.
// ---------------------------------------------------------------------------
__device__ __forceinline__ void sgemm_tile_nt(const float* __restrict__ A,
                                              const float* __restrict__ B,
                                              float* __restrict__ C,
                                              int K, int N)
{
    __shared__ float As[8][128];
    __shared__ float Bs[8][128];

    const int tid = threadIdx.x;
    const int tx = tid & 15;          // 0..15 -> N direction
    const int ty = tid >> 4;          // 0..15 -> M direction
    const int mbase = blockIdx.y * 128;
    const int nbase = blockIdx.x * 128;

    float acc[8][8];
#pragma unroll
    for (int i = 0; i < 8; i++)
#pragma unroll
        for (int j = 0; j < 8; j++) acc[i][j] = 0.0f;

    const int lrow = tid >> 1;            // 0..127
    const int lcg  = (tid & 1) * 4;       // 0 or 4
    const float* Ap = A + (size_t)(mbase + lrow) * K + lcg;
    const float* Bp = B + (size_t)(nbase + lrow) * K + lcg;

    for (int kt = 0; kt < K; kt += 8) {
        float4 av = *(const float4*)(Ap + kt);
        float4 bv = *(const float4*)(Bp + kt);
        As[lcg + 0][lrow] = av.x; As[lcg + 1][lrow] = av.y;
        As[lcg + 2][lrow] = av.z; As[lcg + 3][lrow] = av.w;
        Bs[lcg + 0][lrow] = bv.x; Bs[lcg + 1][lrow] = bv.y;
        Bs[lcg + 2][lrow] = bv.z; Bs[lcg + 3][lrow] = bv.w;
        __syncthreads();

#pragma unroll
        for (int k = 0; k < 8; k++) {
            float a[8], b[8];
            *(float4*)(a)     = *(const float4*)&As[k][ty * 8];
            *(float4*)(a + 4) = *(const float4*)&As[k][ty * 8 + 4];
            *(float4*)(b)     = *(const float4*)&Bs[k][tx * 8];
            *(float4*)(b + 4) = *(const float4*)&Bs[k][tx * 8 + 4];
#pragma unroll
            for (int i = 0; i < 8; i++)
#pragma unroll
                for (int j = 0; j < 8; j++)
                    acc[i][j] += a[i] * b[j];
        }
        __syncthreads();
    }

#pragma unroll
    for (int i = 0; i < 8; i++) {
        float* cp = C + (size_t)(mbase + ty * 8 + i) * N + nbase + tx * 8;
        float4 r0 = make_float4(acc[i][0], acc[i][1], acc[i][2], acc[i][3]);
        float4 r1 = make_float4(acc[i][4], acc[i][5], acc[i][6], acc[i][7]);
        *(float4*)(cp)     = r0;
        *(float4*)(cp + 4) = r1;
    }
}

// QKV projections: z selects Wq/Wk/Wv and the destination buffer.
__global__ void __launch_bounds__(256) qkv_kernel(const float* __restrict__ X,
                                                  const float* __restrict__ Wq,
                                                  const float* __restrict__ Wk,
                                                  const float* __restrict__ Wv)
{
    const float* W = (blockIdx.z == 0) ? Wq : (blockIdx.z == 1) ? Wk : Wv;
    float* dst = (blockIdx.z == 0) ? g_q : (blockIdx.z == 1) ? g_k : g_v;
    sgemm_tile_nt(X, W, dst, DMODEL, DMODEL);
}

// Output projection: out = g_attn @ Wo^T
__global__ void __launch_bounds__(256) proj_kernel(const float* __restrict__ Wo,
                                                   float* __restrict__ out)
{
    sgemm_tile_nt(g_attn, Wo, out, DMODEL, DMODEL);
}

// ---------------------------------------------------------------------------
// RoPE (interleaved pairs) applied in-place to g_q (y=0) and g_k (y=1).
// One thread per (b, t, h, j) pair; j in [0,32).
// ---------------------------------------------------------------------------
__global__ void rope_kernel(const int* __restrict__ pos)
{
    int idx = blockIdx.x * blockDim.x + threadIdx.x;   // < 2^21
    int j = idx & 31;
    int h = (idx >> 5) & 15;
    int t = (idx >> 9) & 2047;
    int b = idx >> 20;

    // inv_freq = theta^(-2j/d_h) = 10000^(-j/32); j/32 exact in fp32.
    float inv = powf(10000.0f, -(float)j * (1.0f / 32.0f));
    float ang = (float)pos[t] * inv;
    float s, c;
    sincosf(ang, &s, &c);

    float* buf = (blockIdx.y == 0) ? g_q : g_k;
    size_t base = ((size_t)(b * SEQ + t)) * DMODEL + h * DHEAD + 2 * j;
    float x1 = buf[base];
    float x2 = buf[base + 1];
    buf[base]     = x1 * c - x2 * s;
    buf[base + 1] = x1 * s + x2 * c;
}

// ---------------------------------------------------------------------------
// Causal flash attention, fp32. One thread per query row (128 rows/block).
// q and o accumulators in registers; K/V tiles (64 keys x 64) in smem.
// Output written back in [b, t, h*dh] layout into g_attn.
// ---------------------------------------------------------------------------
__global__ void __launch_bounds__(128) attn_kernel()
{
    const int b  = blockIdx.z;
    const int h  = blockIdx.y;
    const int qb = blockIdx.x;
    const int tid = threadIdx.x;
    const int r = qb * 128 + tid;

    __shared__ float Ks[64][68];   // padded to dodge bank conflicts on stores
    __shared__ float Vs[64][68];

    float q[DHEAD], o[DHEAD];
    const float* qp = g_q + ((size_t)(b * SEQ + r)) * DMODEL + h * DHEAD;
#pragma unroll
    for (int i = 0; i < DHEAD; i += 4) {
        float4 v4 = *(const float4*)(qp + i);
        q[i]     = v4.x * 0.125f;   // fold 1/sqrt(64)
        q[i + 1] = v4.y * 0.125f;
        q[i + 2] = v4.z * 0.125f;
        q[i + 3] = v4.w * 0.125f;
    }
#pragma unroll
    for (int i = 0; i < DHEAD; i++) o[i] = 0.0f;
    float m = -1e30f, l = 0.0f;

    const int lrow = tid >> 1;         // 0..63
    const int lc   = (tid & 1) * 32;   // 0 or 32
    const int ntiles = 2 * qb + 2;     // key tiles of 64 covering [0, qb*128+128)

    for (int kt = 0; kt < ntiles; kt++) {
        const size_t kb = ((size_t)(b * SEQ + kt * 64 + lrow)) * DMODEL + h * DHEAD + lc;
#pragma unroll
        for (int i = 0; i < 32; i += 4) {
            *(float4*)&Ks[lrow][lc + i] = *(const float4*)(g_k + kb + i);
            *(float4*)&Vs[lrow][lc + i] = *(const float4*)(g_v + kb + i);
        }
        __syncthreads();

        int jend = r - kt * 64 + 1;
        if (jend > 64) jend = 64;

        for (int j = 0; j < jend; j += 4) {
            float s0 = 0.f, s1 = 0.f, s2 = 0.f, s3 = 0.f;
#pragma unroll
            for (int i = 0; i < DHEAD; i += 4) {
                float4 k0 = *(const float4*)&Ks[j][i];
                float4 k1 = *(const float4*)&Ks[j + 1][i];
                float4 k2 = *(const float4*)&Ks[j + 2][i];
                float4 k3 = *(const float4*)&Ks[j + 3][i];
                s0 += q[i] * k0.x + q[i + 1] * k0.y + q[i + 2] * k0.z + q[i + 3] * k0.w;
                s1 += q[i] * k1.x + q[i + 1] * k1.y + q[i + 2] * k1.z + q[i + 3] * k1.w;
                s2 += q[i] * k2.x + q[i + 1] * k2.y + q[i + 2] * k2.z + q[i + 3] * k2.w;
                s3 += q[i] * k3.x + q[i + 1] * k3.y + q[i + 2] * k3.z + q[i + 3] * k3.w;
            }
            bool v1 = (j + 1 < jend), v2 = (j + 2 < jend), v3 = (j + 3 < jend);
            if (!v1) s1 = -1e30f;
            if (!v2) s2 = -1e30f;
            if (!v3) s3 = -1e30f;

            float smax = fmaxf(fmaxf(s0, s1), fmaxf(s2, s3));
            float mnew = fmaxf(m, smax);
            float corr = __expf(m - mnew);
            float p0 = __expf(s0 - mnew);
            float p1 = v1 ? __expf(s1 - mnew) : 0.0f;
            float p2 = v2 ? __expf(s2 - mnew) : 0.0f;
            float p3 = v3 ? __expf(s3 - mnew) : 0.0f;
            l = l * corr + (p0 + p1) + (p2 + p3);
            m = mnew;

#pragma unroll
            for (int i = 0; i < DHEAD; i += 4) {
                float4 w0 = *(const float4*)&Vs[j][i];
                float4 w1 = *(const float4*)&Vs[j + 1][i];
                float4 w2 = *(const float4*)&Vs[j + 2][i];
                float4 w3 = *(const float4*)&Vs[j + 3][i];
                o[i]     = o[i]     * corr + p0 * w0.x + p1 * w1.x + p2 * w2.x + p3 * w3.x;
                o[i + 1] = o[i + 1] * corr + p0 * w0.y + p1 * w1.y + p2 * w2.y + p3 * w3.y;
                o[i + 2] = o[i + 2] * corr + p0 * w0.z + p1 * w1.z + p2 * w2.z + p3 * w3.z;
                o[i + 3] = o[i + 3] * corr + p0 * w0.w + p1 * w1.w + p2 * w2.w + p3 * w3.w;
            }
        }
        __syncthreads();
    }

    float invl = 1.0f / l;
    float* op = g_attn + ((size_t)(b * SEQ + r)) * DMODEL + h * DHEAD;
#pragma unroll
    for (int i = 0; i < DHEAD; i += 4) {
        float4 v4;
        v4.x = o[i] * invl;
        v4.y = o[i + 1] * invl;
        v4.z = o[i + 2] * invl;
        v4.w = o[i + 3] * invl;
        *(float4*)(op + i) = v4;
    }
}

// ---------------------------------------------------------------------------
extern "C" void kernel_launch(void* const* d_in, const int* in_sizes, int n_in,
                              void* d_out, int out_size)
{
    const float* X  = (const float*)d_in[0];
    const float* Wq = (const float*)d_in[1];
    const float* Wk = (const float*)d_in[2];
    const float* Wv = (const float*)d_in[3];
    const float* Wo = (const float*)d_in[4];
    const int*  pos = (const int*)d_in[5];

    // 1) QKV projections (fused over z)
    qkv_kernel<<<dim3(DMODEL / 128, BT / 128, 3), 256>>>(X, Wq, Wk, Wv);

    // 2) RoPE on Q (y=0) and K (y=1)
    rope_kernel<<<dim3((BATCH * SEQ * NHEAD * 32) / 256, 2), 256>>>(pos);

    // 3) Causal flash attention
    attn_kernel<<<dim3(SEQ / 128, NHEAD, BATCH), 128>>>();

    // 4) Output projection into d_out
    proj_kernel<<<dim3(DMODEL / 128, BT / 128, 1), 256>>>(Wo, (float*)d_out);
}

// round 2
// speedup vs baseline: 4.2502x; 4.2502x over previous
#include <cuda_runtime.h>
#include <cuda_bf16.h>
#include <math.h>
#include <stdint.h>

#define BATCH   2
#define SEQ     2048
#define DMODEL  1024
#define NHEAD   16
#define DHEAD   64
#define BT      (BATCH * SEQ)

// Scratch (device globals; no allocation allowed)
__device__ float g_q[BT * DMODEL];
__device__ float g_k[BT * DMODEL];
__device__ float g_v[BT * DMODEL];
__device__ float g_attn[BT * DMODEL];

// fp32 -> tf32 (round-to-nearest-away) as raw b32
__device__ __forceinline__ uint32_t f2tf(float f) {
    uint32_t u;
    asm("cvt.rna.tf32.f32 %0, %1;" : "=r"(u) : "f"(f));
    return u;
}

// mma.sync m16n8k8 tf32, fp32 accumulate (D = A*B + D)
__device__ __forceinline__ void mma_tf32(float c[4], const uint32_t a[4], const uint32_t b[2]) {
    asm volatile(
        "mma.sync.aligned.m16n8k8.row.col.f32.tf32.tf32.f32 "
        "{%0,%1,%2,%3}, {%4,%5,%6,%7}, {%8,%9}, {%0,%1,%2,%3};"
        : "+f"(c[0]), "+f"(c[1]), "+f"(c[2]), "+f"(c[3])
        : "r"(a[0]), "r"(a[1]), "r"(a[2]), "r"(a[3]), "r"(b[0]), "r"(b[1]));
}

// ---------------------------------------------------------------------------
// TF32 tensor-core GEMM tile: C[m,n] = sum_k A[m,k]*B[n,k]
// Block 128x128, K-tile 16, 256 threads = 8 warps (2x4), warp tile 64x32.
// Smem layout stride 20 words -> bank = 4*row + k (conflict-free frag reads).
// ---------------------------------------------------------------------------
__device__ __forceinline__ void gemm_tile_tf32(const float* __restrict__ A,
                                               const float* __restrict__ B,
                                               float* __restrict__ C)
{
    __shared__ uint32_t As[2][128 * 20];
    __shared__ uint32_t Bs[2][128 * 20];

    const int tid  = threadIdx.x;
    const int warp = tid >> 5, lane = tid & 31;
    const int wm = warp >> 2, wn = warp & 3;   // warp grid 2 (M) x 4 (N)
    const int g  = lane >> 2, qd = lane & 3;   // group-of-4 id, quad id
    const int mbase = blockIdx.y * 128;
    const int nbase = blockIdx.x * 128;

    const int lrow = tid >> 1;          // 0..127
    const int lk   = (tid & 1) * 8;     // 0 or 8 (8 consecutive k per thread)
    const float* Ap = A + (size_t)(mbase + lrow) * DMODEL + lk;
    const float* Bp = B + (size_t)(nbase + lrow) * DMODEL + lk;
    uint32_t* aSt0 = &As[0][lrow * 20 + lk];
    uint32_t* bSt0 = &Bs[0][lrow * 20 + lk];
    uint32_t* aSt1 = &As[1][lrow * 20 + lk];
    uint32_t* bSt1 = &Bs[1][lrow * 20 + lk];

    float acc[4][4][4];
#pragma unroll
    for (int i = 0; i < 4; i++)
#pragma unroll
        for (int j = 0; j < 4; j++)
#pragma unroll
            for (int r = 0; r < 4; r++) acc[i][j][r] = 0.0f;

    // preload tile 0
    {
        float4 a0 = *(const float4*)(Ap), a1 = *(const float4*)(Ap + 4);
        float4 b0 = *(const float4*)(Bp), b1 = *(const float4*)(Bp + 4);
        uint4 u;
        u.x = f2tf(a0.x); u.y = f2tf(a0.y); u.z = f2tf(a0.z); u.w = f2tf(a0.w);
        *(uint4*)(aSt0) = u;
        u.x = f2tf(a1.x); u.y = f2tf(a1.y); u.z = f2tf(a1.z); u.w = f2tf(a1.w);
        *(uint4*)(aSt0 + 4) = u;
        u.x = f2tf(b0.x); u.y = f2tf(b0.y); u.z = f2tf(b0.z); u.w = f2tf(b0.w);
        *(uint4*)(bSt0) = u;
        u.x = f2tf(b1.x); u.y = f2tf(b1.y); u.z = f2tf(b1.z); u.w = f2tf(b1.w);
        *(uint4*)(bSt0 + 4) = u;
    }
    __syncthreads();

    const int NK = DMODEL / 16;   // 64
    for (int kt = 0; kt < NK; kt++) {
        const int cur = kt & 1;
        float4 pa0, pa1, pb0, pb1;
        if (kt + 1 < NK) {
            const float* Ap2 = Ap + (kt + 1) * 16;
            const float* Bp2 = Bp + (kt + 1) * 16;
            pa0 = *(const float4*)(Ap2);  pa1 = *(const float4*)(Ap2 + 4);
            pb0 = *(const float4*)(Bp2);  pb1 = *(const float4*)(Bp2 + 4);
        }

        const uint32_t* Ac = As[cur];
        const uint32_t* Bc = Bs[cur];
#pragma unroll
        for (int ks = 0; ks < 2; ks++) {
            uint32_t af[4][4], bf[4][2];
#pragma unroll
            for (int mf = 0; mf < 4; mf++) {
                const uint32_t* p = &Ac[(wm * 64 + mf * 16 + g) * 20 + ks * 8 + qd];
                af[mf][0] = p[0];
                af[mf][1] = p[8 * 20];
                af[mf][2] = p[4];
                af[mf][3] = p[8 * 20 + 4];
            }
#pragma unroll
            for (int nf = 0; nf < 4; nf++) {
                const uint32_t* p = &Bc[(wn * 32 + nf * 8 + g) * 20 + ks * 8 + qd];
                bf[nf][0] = p[0];
                bf[nf][1] = p[4];
            }
#pragma unroll
            for (int mf = 0; mf < 4; mf++)
#pragma unroll
                for (int nf = 0; nf < 4; nf++)
                    mma_tf32(acc[mf][nf], af[mf], bf[nf]);
        }

        if (kt + 1 < NK) {
            uint32_t* aSt = (cur ? aSt0 : aSt1);
            uint32_t* bSt = (cur ? bSt0 : bSt1);
            uint4 u;
            u.x = f2tf(pa0.x); u.y = f2tf(pa0.y); u.z = f2tf(pa0.z); u.w = f2tf(pa0.w);
            *(uint4*)(aSt) = u;
            u.x = f2tf(pa1.x); u.y = f2tf(pa1.y); u.z = f2tf(pa1.z); u.w = f2tf(pa1.w);
            *(uint4*)(aSt + 4) = u;
            u.x = f2tf(pb0.x); u.y = f2tf(pb0.y); u.z = f2tf(pb0.z); u.w = f2tf(pb0.w);
            *(uint4*)(bSt) = u;
            u.x = f2tf(pb1.x); u.y = f2tf(pb1.y); u.z = f2tf(pb1.z); u.w = f2tf(pb1.w);
            *(uint4*)(bSt + 4) = u;
        }
        __syncthreads();
    }

    // epilogue
#pragma unroll
    for (int mf = 0; mf < 4; mf++) {
        const int r0 = mbase + wm * 64 + mf * 16 + g;
        const int r1 = r0 + 8;
#pragma unroll
        for (int nf = 0; nf < 4; nf++) {
            const int col = nbase + wn * 32 + nf * 8 + 2 * qd;
            *(float2*)&C[(size_t)r0 * DMODEL + col] = make_float2(acc[mf][nf][0], acc[mf][nf][1]);
            *(float2*)&C[(size_t)r1 * DMODEL + col] = make_float2(acc[mf][nf][2], acc[mf][nf][3]);
        }
    }
}

__global__ void __launch_bounds__(256) qkv_kernel(const float* __restrict__ X,
                                                  const float* __restrict__ Wq,
                                                  const float* __restrict__ Wk,
                                                  const float* __restrict__ Wv)
{
    const float* W = (blockIdx.z == 0) ? Wq : (blockIdx.z == 1) ? Wk : Wv;
    float* dst = (blockIdx.z == 0) ? g_q : (blockIdx.z == 1) ? g_k : g_v;
    gemm_tile_tf32(X, W, dst);
}

__global__ void __launch_bounds__(256) proj_kernel(const float* __restrict__ Wo,
                                                   float* __restrict__ out)
{
    gemm_tile_tf32(g_attn, Wo, out);
}

// ---------------------------------------------------------------------------
// RoPE (interleaved pairs), in-place on g_q (y=0) and g_k (y=1)
// ---------------------------------------------------------------------------
__global__ void rope_kernel(const int* __restrict__ pos)
{
    int idx = blockIdx.x * blockDim.x + threadIdx.x;
    int j = idx & 31;
    int h = (idx >> 5) & 15;
    int t = (idx >> 9) & 2047;
    int b = idx >> 20;

    float inv = powf(10000.0f, -(float)j * (1.0f / 32.0f));
    float ang = (float)pos[t] * inv;
    float s, c;
    sincosf(ang, &s, &c);

    float* buf = (blockIdx.y == 0) ? g_q : g_k;
    size_t base = ((size_t)(b * SEQ + t)) * DMODEL + h * DHEAD + 2 * j;
    float x1 = buf[base];
    float x2 = buf[base + 1];
    buf[base]     = x1 * c - x2 * s;
    buf[base + 1] = x1 * s + x2 * c;
}

// ---------------------------------------------------------------------------
// Flash attention with tf32 tensor cores.
// Block: 64 queries, 4 warps (16 q-rows each). Key tiles of 64.
// QK^T and P.V both via mma.m16n8k8.tf32. P converted C-layout -> A-layout
// through smem (union'd with the K tile region).
// ---------------------------------------------------------------------------
__global__ void __launch_bounds__(128) attn_kernel()
{
    __shared__ uint32_t U[4352];        // Ks[64][68]  OR  Ps[4][16][68]
    __shared__ uint32_t Vs[64 * 72];    // Vs[64][72]

    const int b = blockIdx.z, h = blockIdx.y, qt = blockIdx.x;
    const int tid = threadIdx.x, warp = tid >> 5, lane = tid & 31;
    const int g = lane >> 2, qd = lane & 3;

    const int r0 = qt * 64 + warp * 16 + g;   // absolute query rows
    const int r1 = r0 + 8;

    // Q fragments (scaled by 1/sqrt(d_h), tf32)
    uint32_t qa[8][4];
    const float* q0p = g_q + ((size_t)(b * SEQ + r0)) * DMODEL + h * DHEAD;
    const float* q1p = g_q + ((size_t)(b * SEQ + r1)) * DMODEL + h * DHEAD;
#pragma unroll
    for (int s = 0; s < 8; s++) {
        qa[s][0] = f2tf(q0p[s * 8 + qd]     * 0.125f);
        qa[s][1] = f2tf(q1p[s * 8 + qd]     * 0.125f);
        qa[s][2] = f2tf(q0p[s * 8 + qd + 4] * 0.125f);
        qa[s][3] = f2tf(q1p[s * 8 + qd + 4] * 0.125f);
    }

    float oacc[8][4];
#pragma unroll
    for (int i = 0; i < 8; i++)
#pragma unroll
        for (int r = 0; r < 4; r++) oacc[i][r] = 0.0f;
    float m0 = -1e30f, m1 = -1e30f, l0 = 0.0f, l1 = 0.0f;

    const int lrow = tid >> 1;          // 0..63
    const int lc   = (tid & 1) * 32;    // 0 or 32
    const int ntiles = qt + 1;

    for (int kt = 0; kt < ntiles; kt++) {
        __syncthreads();   // prior-iteration P/V reads complete
        {
            const size_t gb = ((size_t)(b * SEQ + kt * 64 + lrow)) * DMODEL + h * DHEAD + lc;
            const float* kp = g_k + gb;
            const float* vp = g_v + gb;
#pragma unroll
            for (int i = 0; i < 32; i += 4) {
                float4 kv = *(const float4*)(kp + i);
                uint4 u;
                u.x = f2tf(kv.x); u.y = f2tf(kv.y); u.z = f2tf(kv.z); u.w = f2tf(kv.w);
                *(uint4*)&U[lrow * 68 + lc + i] = u;
                float4 vv = *(const float4*)(vp + i);
                u.x = f2tf(vv.x); u.y = f2tf(vv.y); u.z = f2tf(vv.z); u.w = f2tf(vv.w);
                *(uint4*)&Vs[lrow * 72 + lc + i] = u;
            }
        }
        __syncthreads();

        // S = Q . K^T  (per warp: 16 x 64)
        float sacc[8][4];
#pragma unroll
        for (int nf = 0; nf < 8; nf++) {
            sacc[nf][0] = sacc[nf][1] = sacc[nf][2] = sacc[nf][3] = 0.0f;
#pragma unroll
            for (int s = 0; s < 8; s++) {
                uint32_t bf[2];
                const uint32_t* kb = &U[(nf * 8 + g) * 68 + s * 8 + qd];
                bf[0] = kb[0];
                bf[1] = kb[4];
                mma_tf32(sacc[nf], qa[s], bf);
            }
        }

        // causal mask (only the diagonal tile needs it)
        if (kt == ntiles - 1) {
#pragma unroll
            for (int nf = 0; nf < 8; nf++) {
                int c0 = kt * 64 + nf * 8 + 2 * qd;
                if (c0 > r0)     sacc[nf][0] = -1e30f;
                if (c0 + 1 > r0) sacc[nf][1] = -1e30f;
                if (c0 > r1)     sacc[nf][2] = -1e30f;
                if (c0 + 1 > r1) sacc[nf][3] = -1e30f;
            }
        }

        // online softmax
        float mx0 = -1e30f, mx1 = -1e30f;
#pragma unroll
        for (int nf = 0; nf < 8; nf++) {
            mx0 = fmaxf(mx0, fmaxf(sacc[nf][0], sacc[nf][1]));
            mx1 = fmaxf(mx1, fmaxf(sacc[nf][2], sacc[nf][3]));
        }
        mx0 = fmaxf(mx0, __shfl_xor_sync(0xffffffffu, mx0, 1));
        mx0 = fmaxf(mx0, __shfl_xor_sync(0xffffffffu, mx0, 2));
        mx1 = fmaxf(mx1, __shfl_xor_sync(0xffffffffu, mx1, 1));
        mx1 = fmaxf(mx1, __shfl_xor_sync(0xffffffffu, mx1, 2));

        float mn0 = fmaxf(m0, mx0), mn1 = fmaxf(m1, mx1);
        float cr0 = __expf(m0 - mn0), cr1 = __expf(m1 - mn1);
        float sum0 = 0.0f, sum1 = 0.0f;
#pragma unroll
        for (int nf = 0; nf < 8; nf++) {
            sacc[nf][0] = __expf(sacc[nf][0] - mn0);
            sacc[nf][1] = __expf(sacc[nf][1] - mn0);
            sacc[nf][2] = __expf(sacc[nf][2] - mn1);
            sacc[nf][3] = __expf(sacc[nf][3] - mn1);
            sum0 += sacc[nf][0] + sacc[nf][1];
            sum1 += sacc[nf][2] + sacc[nf][3];
        }
        sum0 += __shfl_xor_sync(0xffffffffu, sum0, 1);
        sum0 += __shfl_xor_sync(0xffffffffu, sum0, 2);
        sum1 += __shfl_xor_sync(0xffffffffu, sum1, 1);
        sum1 += __shfl_xor_sync(0xffffffffu, sum1, 2);
        l0 = l0 * cr0 + sum0;
        l1 = l1 * cr1 + sum1;
        m0 = mn0; m1 = mn1;
#pragma unroll
        for (int nf = 0; nf < 8; nf++) {
            oacc[nf][0] *= cr0; oacc[nf][1] *= cr0;
            oacc[nf][2] *= cr1; oacc[nf][3] *= cr1;
        }

        __syncthreads();   // all warps done reading Ks before overwriting with P

        // store P (C-layout -> smem), then reload in A-layout
        uint32_t* Pw = &U[warp * 1088];
#pragma unroll
        for (int nf = 0; nf < 8; nf++) {
            const int c = nf * 8 + 2 * qd;
            uint2 lo = make_uint2(f2tf(sacc[nf][0]), f2tf(sacc[nf][1]));
            *(uint2*)&Pw[g * 68 + c] = lo;
            uint2 hi = make_uint2(f2tf(sacc[nf][2]), f2tf(sacc[nf][3]));
            *(uint2*)&Pw[(g + 8) * 68 + c] = hi;
        }
        __syncwarp();

        // O += P . V
#pragma unroll
        for (int s = 0; s < 8; s++) {
            uint32_t af[4];
            af[0] = Pw[g * 68 + s * 8 + qd];
            af[1] = Pw[(g + 8) * 68 + s * 8 + qd];
            af[2] = Pw[g * 68 + s * 8 + qd + 4];
            af[3] = Pw[(g + 8) * 68 + s * 8 + qd + 4];
#pragma unroll
            for (int nf = 0; nf < 8; nf++) {
                uint32_t bf[2];
                const uint32_t* vb = &Vs[(s * 8 + qd) * 72 + nf * 8 + g];
                bf[0] = vb[0];
                bf[1] = vb[4 * 72];
                mma_tf32(oacc[nf], af, bf);
            }
        }
    }

    // write O / l
    const float il0 = 1.0f / l0, il1 = 1.0f / l1;
    float* o0 = g_attn + ((size_t)(b * SEQ + r0)) * DMODEL + h * DHEAD;
    float* o1 = g_attn + ((size_t)(b * SEQ + r1)) * DMODEL + h * DHEAD;
#pragma unroll
    for (int nf = 0; nf < 8; nf++) {
        const int c = nf * 8 + 2 * qd;
        *(float2*)&o0[c] = make_float2(oacc[nf][0] * il0, oacc[nf][1] * il0);
        *(float2*)&o1[c] = make_float2(oacc[nf][2] * il1, oacc[nf][3] * il1);
    }
}

// ---------------------------------------------------------------------------
extern "C" void kernel_launch(void* const* d_in, const int* in_sizes, int n_in,
                              void* d_out, int out_size)
{
    const float* X  = (const float*)d_in[0];
    const float* Wq = (const float*)d_in[1];
    const float* Wk = (const float*)d_in[2];
    const float* Wv = (const float*)d_in[3];
    const float* Wo = (const float*)d_in[4];
    const int*  pos = (const int*)d_in[5];

    qkv_kernel<<<dim3(DMODEL / 128, BT / 128, 3), 256>>>(X, Wq, Wk, Wv);
    rope_kernel<<<dim3((BATCH * SEQ * NHEAD * 32) / 256, 2), 256>>>(pos);
    attn_kernel<<<dim3(SEQ / 64, NHEAD, BATCH), 128>>>();
    proj_kernel<<<dim3(DMODEL / 128, BT / 128, 1), 256>>>(Wo, (float*)d_out);
}

// round 5
// speedup vs baseline: 5.6277x; 1.3241x over previous
#include <cuda_runtime.h>
#include <cuda_bf16.h>
#include <math.h>
#include <stdint.h>

#define BATCH   2
#define SEQ     2048
#define DMODEL  1024
#define NHEAD   16
#define DHEAD   64
#define BT      (BATCH * SEQ)

// Scratch (device globals; no allocation allowed)
__device__ float g_q[BT * DMODEL];
__device__ float g_k[BT * DMODEL];
__device__ float g_v[BT * DMODEL];
__device__ float g_attn[BT * DMODEL];

// fp32 -> tf32 (round-to-nearest-away) as raw b32
__device__ __forceinline__ uint32_t f2tf(float f) {
    uint32_t u;
    asm("cvt.rna.tf32.f32 %0, %1;" : "=r"(u) : "f"(f));
    return u;
}

__device__ __forceinline__ uint32_t smem_u32(const void* p) {
    uint32_t a;
    asm("{ .reg .u64 t; cvta.to.shared.u64 t, %1; cvt.u32.u64 %0, t; }" : "=r"(a) : "l"(p));
    return a;
}

// mma.sync m16n8k8 tf32, fp32 accumulate (D = A*B + D)
__device__ __forceinline__ void mma_tf32(float c[4], const uint32_t a[4], const uint32_t b[2]) {
    asm volatile(
        "mma.sync.aligned.m16n8k8.row.col.f32.tf32.tf32.f32 "
        "{%0,%1,%2,%3}, {%4,%5,%6,%7}, {%8,%9}, {%0,%1,%2,%3};"
        : "+f"(c[0]), "+f"(c[1]), "+f"(c[2]), "+f"(c[3])
        : "r"(a[0]), "r"(a[1]), "r"(a[2]), "r"(a[3]), "r"(b[0]), "r"(b[1]));
}

__device__ __forceinline__ void cp16(uint32_t dst, const void* src) {
    asm volatile("cp.async.cg.shared.global [%0], [%1], 16;" :: "r"(dst), "l"(src));
}
__device__ __forceinline__ void cp_commit() {
    asm volatile("cp.async.commit_group;");
}
__device__ __forceinline__ void cp_wait2() {
    asm volatile("cp.async.wait_group 2;");
}

// ---------------------------------------------------------------------------
// TF32 tensor-core GEMM: C[m,n] = sum_k A[m,k]*B[n,k]
// Block 128x128, 256 threads = 8 warps (2x4), warp tile 64x32, K-stage 16.
// 4-stage cp.async pipeline, one __syncthreads per k-iteration.
// Smem per stage: A/B 128 rows x 16 floats, row stride 20 (conflict-free).
// Optional fused RoPE on the epilogue (rope=1 for Q/K projections).
// ---------------------------------------------------------------------------
#define GEMM_DSM 81920   // 4 stages x (10240 A + 10240 B)

__device__ __forceinline__ void gemm_tc(const float* __restrict__ A,
                                        const float* __restrict__ B,
                                        float* __restrict__ C,
                                        int rope, const int* __restrict__ pos)
{
    extern __shared__ float dsm[];
    const uint32_t sb = smem_u32(dsm);

    const int tid  = threadIdx.x;
    const int warp = tid >> 5, lane = tid & 31;
    const int wm = warp >> 2, wn = warp & 3;
    const int g  = lane >> 2, qd = lane & 3;
    const int mbase = blockIdx.y * 128;
    const int nbase = blockIdx.x * 128;

    // producer geometry: 2 threads per row, 8 floats (2x16B) each
    const int r  = tid >> 1;
    const int cq = (tid & 1) * 2;
    const float* Arow = A + (size_t)(mbase + r) * DMODEL + cq * 4;
    const float* Brow = B + (size_t)(nbase + r) * DMODEL + cq * 4;
    const uint32_t dOff = (uint32_t)r * 80u + (uint32_t)cq * 16u;

    float acc[4][4][4];
#pragma unroll
    for (int i = 0; i < 4; i++)
#pragma unroll
        for (int j = 0; j < 4; j++)
#pragma unroll
            for (int k = 0; k < 4; k++) acc[i][j][k] = 0.0f;

    // prologue: stages 0..2
#pragma unroll
    for (int s = 0; s < 3; s++) {
        const uint32_t da = sb + (uint32_t)s * 10240u + dOff;
        const uint32_t db = da + 40960u;
        cp16(da,      Arow + s * 16);
        cp16(da + 16, Arow + s * 16 + 4);
        cp16(db,      Brow + s * 16);
        cp16(db + 16, Brow + s * 16 + 4);
        cp_commit();
    }

    const int NK = DMODEL / 16;   // 64
    for (int kt = 0; kt < NK; kt++) {
        cp_wait2();
        __syncthreads();

        // prefetch stage kt+3 (empty commit past the end keeps group counts aligned)
        if (kt + 3 < NK) {
            const int s = kt + 3;
            const uint32_t da = sb + (uint32_t)(s & 3) * 10240u + dOff;
            const uint32_t db = da + 40960u;
            cp16(da,      Arow + s * 16);
            cp16(da + 16, Arow + s * 16 + 4);
            cp16(db,      Brow + s * 16);
            cp16(db + 16, Brow + s * 16 + 4);
        }
        cp_commit();

        const float* Ast = dsm + (kt & 3) * 2560;
        const float* Bst = dsm + 10240 + (kt & 3) * 2560;
#pragma unroll
        for (int ks = 0; ks < 2; ks++) {
            uint32_t af[4][4], bf[4][2];
#pragma unroll
            for (int mf = 0; mf < 4; mf++) {
                const float* p = &Ast[(wm * 64 + mf * 16 + g) * 20 + ks * 8 + qd];
                af[mf][0] = f2tf(p[0]);
                af[mf][1] = f2tf(p[160]);
                af[mf][2] = f2tf(p[4]);
                af[mf][3] = f2tf(p[164]);
            }
#pragma unroll
            for (int nf = 0; nf < 4; nf++) {
                const float* p = &Bst[(wn * 32 + nf * 8 + g) * 20 + ks * 8 + qd];
                bf[nf][0] = f2tf(p[0]);
                bf[nf][1] = f2tf(p[4]);
            }
#pragma unroll
            for (int mf = 0; mf < 4; mf++)
#pragma unroll
                for (int nf = 0; nf < 4; nf++)
                    mma_tf32(acc[mf][nf], af[mf], bf[nf]);
        }
    }

    // epilogue (optionally fused RoPE: each thread holds the (even,odd) pair)
#pragma unroll
    for (int mf = 0; mf < 4; mf++) {
        const int r0 = mbase + wm * 64 + mf * 16 + g;
        const int r1 = r0 + 8;
        float p0 = 0.0f, p1 = 0.0f;
        if (rope) {
            p0 = (float)pos[r0 & (SEQ - 1)];
            p1 = (float)pos[r1 & (SEQ - 1)];
        }
#pragma unroll
        for (int nf = 0; nf < 4; nf++) {
            const int col = nbase + wn * 32 + nf * 8 + 2 * qd;
            float a0 = acc[mf][nf][0], a1 = acc[mf][nf][1];
            float a2 = acc[mf][nf][2], a3 = acc[mf][nf][3];
            if (rope) {
                const int j = (col >> 1) & 31;
                const float inv = exp2f((float)j * -0.41524101186092029f);
                float s0, c0, s1, c1;
                sincosf(p0 * inv, &s0, &c0);
                sincosf(p1 * inv, &s1, &c1);
                float n0 = a0 * c0 - a1 * s0;
                float n1 = a0 * s0 + a1 * c0;
                float n2 = a2 * c1 - a3 * s1;
                float n3 = a2 * s1 + a3 * c1;
                a0 = n0; a1 = n1; a2 = n2; a3 = n3;
            }
            *(float2*)&C[(size_t)r0 * DMODEL + col] = make_float2(a0, a1);
            *(float2*)&C[(size_t)r1 * DMODEL + col] = make_float2(a2, a3);
        }
    }
}

__global__ void __launch_bounds__(256, 2) qkv_kernel(const float* __restrict__ X,
                                                     const float* __restrict__ Wq,
                                                     const float* __restrict__ Wk,
                                                     const float* __restrict__ Wv,
                                                     const int* __restrict__ pos)
{
    const float* W = (blockIdx.z == 0) ? Wq : (blockIdx.z == 1) ? Wk : Wv;
    float* dst = (blockIdx.z == 0) ? g_q : (blockIdx.z == 1) ? g_k : g_v;
    gemm_tc(X, W, dst, blockIdx.z < 2 ? 1 : 0, pos);
}

__global__ void __launch_bounds__(256, 2) proj_kernel(const float* __restrict__ Wo,
                                                      float* __restrict__ out)
{
    gemm_tc(g_attn, Wo, out, 0, (const int*)0);
}

// ---------------------------------------------------------------------------
// Causal flash attention, tf32 warp MMA.
// 256 threads / 128 queries per block (8 warps x 16 q-rows), key tiles of 64.
// P transposed C-frag -> A-frag via register shuffles (no smem round-trip).
// ---------------------------------------------------------------------------
__global__ void __launch_bounds__(256) attn_kernel()
{
    __shared__ uint32_t Ks[64 * 68];
    __shared__ uint32_t Vs[64 * 72];

    const int b = blockIdx.z, h = blockIdx.y;
    const int qt = gridDim.x - 1 - blockIdx.x;      // heavy blocks first
    const int tid = threadIdx.x, warp = tid >> 5, lane = tid & 31;
    const int g = lane >> 2, qd = lane & 3;

    const int r0 = qt * 128 + warp * 16 + g;
    const int r1 = r0 + 8;
    const int wrow_lo = qt * 128 + warp * 16;       // warp's min q row
    const int wrow_hi = wrow_lo + 15;               // warp's max q row

    // Q fragments (scaled by 1/sqrt(64))
    uint32_t qa[8][4];
    const float* q0p = g_q + ((size_t)(b * SEQ + r0)) * DMODEL + h * DHEAD;
    const float* q1p = g_q + ((size_t)(b * SEQ + r1)) * DMODEL + h * DHEAD;
#pragma unroll
    for (int s = 0; s < 8; s++) {
        qa[s][0] = f2tf(q0p[s * 8 + qd]     * 0.125f);
        qa[s][1] = f2tf(q1p[s * 8 + qd]     * 0.125f);
        qa[s][2] = f2tf(q0p[s * 8 + qd + 4] * 0.125f);
        qa[s][3] = f2tf(q1p[s * 8 + qd + 4] * 0.125f);
    }

    float oacc[8][4];
#pragma unroll
    for (int i = 0; i < 8; i++)
#pragma unroll
        for (int k = 0; k < 4; k++) oacc[i][k] = 0.0f;
    float m0 = -1e30f, m1 = -1e30f, l0 = 0.0f, l1 = 0.0f;

    const int lrow = tid >> 2;            // 0..63
    const int lc   = (tid & 3) * 16;      // 0,16,32,48
    const int ntiles = 2 * qt + 2;

    for (int kt = 0; kt < ntiles; kt++) {
        __syncthreads();   // everyone done with previous tile's smem
        {
            const size_t gb = ((size_t)(b * SEQ + kt * 64 + lrow)) * DMODEL + h * DHEAD + lc;
            const float* kp = g_k + gb;
            const float* vp = g_v + gb;
#pragma unroll
            for (int i = 0; i < 16; i += 4) {
                float4 kv = *(const float4*)(kp + i);
                uint4 u;
                u.x = f2tf(kv.x); u.y = f2tf(kv.y); u.z = f2tf(kv.z); u.w = f2tf(kv.w);
                *(uint4*)&Ks[lrow * 68 + lc + i] = u;
                float4 vv = *(const float4*)(vp + i);
                u.x = f2tf(vv.x); u.y = f2tf(vv.y); u.z = f2tf(vv.z); u.w = f2tf(vv.w);
                *(uint4*)&Vs[lrow * 72 + lc + i] = u;
            }
        }
        __syncthreads();

        const int kbase = kt * 64;
        if (kbase > wrow_hi) continue;            // warp fully above diagonal
        const bool needmask = (kbase + 63 > wrow_lo);

        // S = Q . K^T  (16 x 64 per warp)
        float sacc[8][4];
#pragma unroll
        for (int nf = 0; nf < 8; nf++) {
            sacc[nf][0] = sacc[nf][1] = sacc[nf][2] = sacc[nf][3] = 0.0f;
#pragma unroll
            for (int s = 0; s < 8; s++) {
                uint32_t bf[2];
                const uint32_t* kb = &Ks[(nf * 8 + g) * 68 + s * 8 + qd];
                bf[0] = kb[0];
                bf[1] = kb[4];
                mma_tf32(sacc[nf], qa[s], bf);
            }
        }

        if (needmask) {
#pragma unroll
            for (int nf = 0; nf < 8; nf++) {
                const int c0 = kbase + nf * 8 + 2 * qd;
                if (c0 > r0)     sacc[nf][0] = -1e30f;
                if (c0 + 1 > r0) sacc[nf][1] = -1e30f;
                if (c0 > r1)     sacc[nf][2] = -1e30f;
                if (c0 + 1 > r1) sacc[nf][3] = -1e30f;
            }
        }

        // online softmax
        float mx0 = -1e30f, mx1 = -1e30f;
#pragma unroll
        for (int nf = 0; nf < 8; nf++) {
            mx0 = fmaxf(mx0, fmaxf(sacc[nf][0], sacc[nf][1]));
            mx1 = fmaxf(mx1, fmaxf(sacc[nf][2], sacc[nf][3]));
        }
        mx0 = fmaxf(mx0, __shfl_xor_sync(0xffffffffu, mx0, 1));
        mx0 = fmaxf(mx0, __shfl_xor_sync(0xffffffffu, mx0, 2));
        mx1 = fmaxf(mx1, __shfl_xor_sync(0xffffffffu, mx1, 1));
        mx1 = fmaxf(mx1, __shfl_xor_sync(0xffffffffu, mx1, 2));

        const float mn0 = fmaxf(m0, mx0), mn1 = fmaxf(m1, mx1);
        const float cr0 = __expf(m0 - mn0), cr1 = __expf(m1 - mn1);
        float sum0 = 0.0f, sum1 = 0.0f;
#pragma unroll
        for (int nf = 0; nf < 8; nf++) {
            sacc[nf][0] = __expf(sacc[nf][0] - mn0);
            sacc[nf][1] = __expf(sacc[nf][1] - mn0);
            sacc[nf][2] = __expf(sacc[nf][2] - mn1);
            sacc[nf][3] = __expf(sacc[nf][3] - mn1);
            sum0 += sacc[nf][0] + sacc[nf][1];
            sum1 += sacc[nf][2] + sacc[nf][3];
        }
        sum0 += __shfl_xor_sync(0xffffffffu, sum0, 1);
        sum0 += __shfl_xor_sync(0xffffffffu, sum0, 2);
        sum1 += __shfl_xor_sync(0xffffffffu, sum1, 1);
        sum1 += __shfl_xor_sync(0xffffffffu, sum1, 2);
        l0 = l0 * cr0 + sum0;
        l1 = l1 * cr1 + sum1;
        m0 = mn0; m1 = mn1;
#pragma unroll
        for (int nf = 0; nf < 8; nf++) {
            oacc[nf][0] *= cr0; oacc[nf][1] *= cr0;
            oacc[nf][2] *= cr1; oacc[nf][3] *= cr1;
        }

        // O += P . V, P transposed C-frag -> A-frag in registers.
        // Source lane for col qd is (g*4 + qd/2); for col qd+4 it's +2;
        // parity of qd picks the even/odd accumulator register.
        const int src0 = (lane & 0x1c) | (qd >> 1);
        const int src1 = src0 + 2;
        const bool odd = (qd & 1);
#pragma unroll
        for (int s = 0; s < 8; s++) {
            const float A0 = sacc[s][0], A1 = sacc[s][1];
            const float A2 = sacc[s][2], A3 = sacc[s][3];
            const float x0 = __shfl_sync(0xffffffffu, A0, src0);
            const float x1 = __shfl_sync(0xffffffffu, A1, src0);
            const float y0 = __shfl_sync(0xffffffffu, A2, src0);
            const float y1 = __shfl_sync(0xffffffffu, A3, src0);
            const float z0 = __shfl_sync(0xffffffffu, A0, src1);
            const float z1 = __shfl_sync(0xffffffffu, A1, src1);
            const float w0 = __shfl_sync(0xffffffffu, A2, src1);
            const float w1 = __shfl_sync(0xffffffffu, A3, src1);
            uint32_t af[4];
            af[0] = f2tf(odd ? x1 : x0);   // P[g   ][s*8+qd  ]
            af[1] = f2tf(odd ? y1 : y0);   // P[g+8 ][s*8+qd  ]
            af[2] = f2tf(odd ? z1 : z0);   // P[g   ][s*8+qd+4]
            af[3] = f2tf(odd ? w1 : w0);   // P[g+8 ][s*8+qd+4]
#pragma unroll
            for (int nf = 0; nf < 8; nf++) {
                uint32_t bf[2];
                const uint32_t* vb = &Vs[(s * 8 + qd) * 72 + nf * 8 + g];
                bf[0] = vb[0];
                bf[1] = vb[4 * 72];
                mma_tf32(oacc[nf], af, bf);
            }
        }
    }

    const float il0 = 1.0f / l0, il1 = 1.0f / l1;
    float* o0 = g_attn + ((size_t)(b * SEQ + r0)) * DMODEL + h * DHEAD;
    float* o1 = g_attn + ((size_t)(b * SEQ + r1)) * DMODEL + h * DHEAD;
#pragma unroll
    for (int nf = 0; nf < 8; nf++) {
        const int c = nf * 8 + 2 * qd;
        *(float2*)&o0[c] = make_float2(oacc[nf][0] * il0, oacc[nf][1] * il0);
        *(float2*)&o1[c] = make_float2(oacc[nf][2] * il1, oacc[nf][3] * il1);
    }
}

// ---------------------------------------------------------------------------
extern "C" void kernel_launch(void* const* d_in, const int* in_sizes, int n_in,
                              void* d_out, int out_size)
{
    const float* X  = (const float*)d_in[0];
    const float* Wq = (const float*)d_in[1];
    const float* Wk = (const float*)d_in[2];
    const float* Wv = (const float*)d_in[3];
    const float* Wo = (const float*)d_in[4];
    const int*  pos = (const int*)d_in[5];

    cudaFuncSetAttribute(qkv_kernel,  cudaFuncAttributeMaxDynamicSharedMemorySize, GEMM_DSM);
    cudaFuncSetAttribute(proj_kernel, cudaFuncAttributeMaxDynamicSharedMemorySize, GEMM_DSM);

    qkv_kernel<<<dim3(DMODEL / 128, BT / 128, 3), 256, GEMM_DSM>>>(X, Wq, Wk, Wv, pos);
    attn_kernel<<<dim3(SEQ / 128, NHEAD, BATCH), 256>>>();
    proj_kernel<<<dim3(DMODEL / 128, BT / 128, 1), 256, GEMM_DSM>>>(Wo, (float*)d_out);
}

// round 6
// speedup vs baseline: 5.7244x; 1.0172x over previous
#include <cuda_runtime.h>
#include <cuda_bf16.h>
#include <math.h>
#include <stdint.h>

#define BATCH   2
#define SEQ     2048
#define DMODEL  1024
#define NHEAD   16
#define DHEAD   64
#define BT      (BATCH * SEQ)

// Scratch (device globals; no allocation allowed). All hold tf32-rounded fp32.
__device__ float g_q[BT * DMODEL];
__device__ float g_k[BT * DMODEL];
__device__ float g_v[BT * DMODEL];
__device__ float g_attn[BT * DMODEL];
__device__ float g_xc[BT * DMODEL];            // X pre-rounded to tf32
__device__ float g_w4[4 * DMODEL * DMODEL];    // Wq,Wk,Wv,Wo pre-rounded

// fp32 -> tf32 (round-to-nearest-away) as raw b32
__device__ __forceinline__ uint32_t f2tf(float f) {
    uint32_t u;
    asm("cvt.rna.tf32.f32 %0, %1;" : "=r"(u) : "f"(f));
    return u;
}

__device__ __forceinline__ uint32_t smem_u32(const void* p) {
    uint32_t a;
    asm("{ .reg .u64 t; cvta.to.shared.u64 t, %1; cvt.u32.u64 %0, t; }" : "=r"(a) : "l"(p));
    return a;
}

// mma.sync m16n8k8 tf32, fp32 accumulate (D = A*B + D)
__device__ __forceinline__ void mma_tf32(float c[4], const uint32_t a[4], const uint32_t b[2]) {
    asm volatile(
        "mma.sync.aligned.m16n8k8.row.col.f32.tf32.tf32.f32 "
        "{%0,%1,%2,%3}, {%4,%5,%6,%7}, {%8,%9}, {%0,%1,%2,%3};"
        : "+f"(c[0]), "+f"(c[1]), "+f"(c[2]), "+f"(c[3])
        : "r"(a[0]), "r"(a[1]), "r"(a[2]), "r"(a[3]), "r"(b[0]), "r"(b[1]));
}

__device__ __forceinline__ void cp16(uint32_t dst, const void* src) {
    asm volatile("cp.async.cg.shared.global [%0], [%1], 16;" :: "r"(dst), "l"(src));
}
__device__ __forceinline__ void cp_commit() {
    asm volatile("cp.async.commit_group;");
}
__device__ __forceinline__ void cp_wait2() {
    asm volatile("cp.async.wait_group 2;");
}
__device__ __forceinline__ void cp_wait1() {
    asm volatile("cp.async.wait_group 1;");
}

// ---------------------------------------------------------------------------
// Prepass: round X and the four weights to tf32 once (idempotent rounding).
// ---------------------------------------------------------------------------
__global__ void cvt_kernel(const float* __restrict__ X,
                           const float* __restrict__ Wq,
                           const float* __restrict__ Wk,
                           const float* __restrict__ Wv,
                           const float* __restrict__ Wo)
{
    const int y = blockIdx.y;
    const float* src;
    float* dst;
    int n;
    if (y == 0)      { src = X;  dst = g_xc;                          n = BT * DMODEL; }
    else             { src = (y == 1) ? Wq : (y == 2) ? Wk : (y == 3) ? Wv : Wo;
                       dst = g_w4 + (size_t)(y - 1) * DMODEL * DMODEL; n = DMODEL * DMODEL; }
    const int i = (blockIdx.x * 256 + threadIdx.x) * 4;
    if (i < n) {
        float4 v = *(const float4*)(src + i);
        uint4 u;
        u.x = f2tf(v.x); u.y = f2tf(v.y); u.z = f2tf(v.z); u.w = f2tf(v.w);
        *(uint4*)(dst + i) = u;
    }
}

// ---------------------------------------------------------------------------
// TF32 tensor-core GEMM: C[m,n] = sum_k A[m,k]*B[n,k]; inputs pre-tf32.
// Block 128x128, 8 warps, warp tile 64x32, K-stage 16, 4-stage cp.async.
// Optional fused RoPE on the epilogue; `tfout` rounds stores to tf32.
// ---------------------------------------------------------------------------
#define GEMM_DSM 81920

__device__ __forceinline__ void gemm_tc(const float* __restrict__ A,
                                        const float* __restrict__ B,
                                        float* __restrict__ C,
                                        int rope, const int* __restrict__ pos,
                                        int tfout)
{
    extern __shared__ float dsm[];
    const uint32_t sb = smem_u32(dsm);

    const int tid  = threadIdx.x;
    const int warp = tid >> 5, lane = tid & 31;
    const int wm = warp >> 2, wn = warp & 3;
    const int g  = lane >> 2, qd = lane & 3;
    const int mbase = blockIdx.y * 128;
    const int nbase = blockIdx.x * 128;

    const int r  = tid >> 1;
    const int cq = (tid & 1) * 2;
    const float* Arow = A + (size_t)(mbase + r) * DMODEL + cq * 4;
    const float* Brow = B + (size_t)(nbase + r) * DMODEL + cq * 4;
    const uint32_t dOff = (uint32_t)r * 80u + (uint32_t)cq * 16u;

    float acc[4][4][4];
#pragma unroll
    for (int i = 0; i < 4; i++)
#pragma unroll
        for (int j = 0; j < 4; j++)
#pragma unroll
            for (int k = 0; k < 4; k++) acc[i][j][k] = 0.0f;

#pragma unroll
    for (int s = 0; s < 3; s++) {
        const uint32_t da = sb + (uint32_t)s * 10240u + dOff;
        const uint32_t db = da + 40960u;
        cp16(da,      Arow + s * 16);
        cp16(da + 16, Arow + s * 16 + 4);
        cp16(db,      Brow + s * 16);
        cp16(db + 16, Brow + s * 16 + 4);
        cp_commit();
    }

    const int NK = DMODEL / 16;   // 64
    for (int kt = 0; kt < NK; kt++) {
        cp_wait2();
        __syncthreads();

        if (kt + 3 < NK) {
            const int s = kt + 3;
            const uint32_t da = sb + (uint32_t)(s & 3) * 10240u + dOff;
            const uint32_t db = da + 40960u;
            cp16(da,      Arow + s * 16);
            cp16(da + 16, Arow + s * 16 + 4);
            cp16(db,      Brow + s * 16);
            cp16(db + 16, Brow + s * 16 + 4);
        }
        cp_commit();

        const uint32_t* Ast = (const uint32_t*)(dsm + (kt & 3) * 2560);
        const uint32_t* Bst = (const uint32_t*)(dsm + 10240 + (kt & 3) * 2560);
#pragma unroll
        for (int ks = 0; ks < 2; ks++) {
            uint32_t af[4][4], bf[4][2];
#pragma unroll
            for (int mf = 0; mf < 4; mf++) {
                const uint32_t* p = &Ast[(wm * 64 + mf * 16 + g) * 20 + ks * 8 + qd];
                af[mf][0] = p[0];
                af[mf][1] = p[160];
                af[mf][2] = p[4];
                af[mf][3] = p[164];
            }
#pragma unroll
            for (int nf = 0; nf < 4; nf++) {
                const uint32_t* p = &Bst[(wn * 32 + nf * 8 + g) * 20 + ks * 8 + qd];
                bf[nf][0] = p[0];
                bf[nf][1] = p[4];
            }
#pragma unroll
            for (int mf = 0; mf < 4; mf++)
#pragma unroll
                for (int nf = 0; nf < 4; nf++)
                    mma_tf32(acc[mf][nf], af[mf], bf[nf]);
        }
    }

    // epilogue (optional fused RoPE; optional tf32 rounding of stores)
#pragma unroll
    for (int mf = 0; mf < 4; mf++) {
        const int r0 = mbase + wm * 64 + mf * 16 + g;
        const int r1 = r0 + 8;
        float p0 = 0.0f, p1 = 0.0f;
        if (rope) {
            p0 = (float)pos[r0 & (SEQ - 1)];
            p1 = (float)pos[r1 & (SEQ - 1)];
        }
#pragma unroll
        for (int nf = 0; nf < 4; nf++) {
            const int col = nbase + wn * 32 + nf * 8 + 2 * qd;
            float a0 = acc[mf][nf][0], a1 = acc[mf][nf][1];
            float a2 = acc[mf][nf][2], a3 = acc[mf][nf][3];
            if (rope) {
                const int j = (col >> 1) & 31;
                const float inv = exp2f((float)j * -0.41524101186092029f);
                float s0, c0, s1, c1;
                sincosf(p0 * inv, &s0, &c0);
                sincosf(p1 * inv, &s1, &c1);
                float n0 = a0 * c0 - a1 * s0;
                float n1 = a0 * s0 + a1 * c0;
                float n2 = a2 * c1 - a3 * s1;
                float n3 = a2 * s1 + a3 * c1;
                a0 = n0; a1 = n1; a2 = n2; a3 = n3;
            }
            if (tfout) {
                a0 = __uint_as_float(f2tf(a0));
                a1 = __uint_as_float(f2tf(a1));
                a2 = __uint_as_float(f2tf(a2));
                a3 = __uint_as_float(f2tf(a3));
            }
            *(float2*)&C[(size_t)r0 * DMODEL + col] = make_float2(a0, a1);
            *(float2*)&C[(size_t)r1 * DMODEL + col] = make_float2(a2, a3);
        }
    }
}

__global__ void __launch_bounds__(256, 2) qkv_kernel(const int* __restrict__ pos)
{
    const int z = blockIdx.z;
    const float* W = g_w4 + (size_t)z * DMODEL * DMODEL;
    float* dst = (z == 0) ? g_q : (z == 1) ? g_k : g_v;
    gemm_tc(g_xc, W, dst, z < 2 ? 1 : 0, pos, 1);
}

__global__ void __launch_bounds__(256, 2) proj_kernel(float* __restrict__ out)
{
    gemm_tc(g_attn, g_w4 + (size_t)3 * DMODEL * DMODEL, out, 0, (const int*)0, 0);
}

// ---------------------------------------------------------------------------
// Causal flash attention, tf32 warp MMA, cp.async double-buffered K/V tiles.
// 256 threads / 128 queries per block (8 warps x 16 q-rows), key tiles of 64.
// P transposed C-frag -> A-frag via register shuffles.
// Stage layout (bytes): Ks 64x68x4=17408, Vs 64x72x4=18432; 35840/stage.
// ---------------------------------------------------------------------------
#define ATTN_STAGE 35840
#define ATTN_DSM   (2 * ATTN_STAGE)

__global__ void __launch_bounds__(256) attn_kernel()
{
    extern __shared__ char asm_s[];
    const uint32_t sb = smem_u32(asm_s);

    const int b = blockIdx.z, h = blockIdx.y;
    const int qt = gridDim.x - 1 - blockIdx.x;      // heavy blocks first
    const int tid = threadIdx.x, warp = tid >> 5, lane = tid & 31;
    const int g = lane >> 2, qd = lane & 3;

    const int r0 = qt * 128 + warp * 16 + g;
    const int r1 = r0 + 8;
    const int wrow_lo = qt * 128 + warp * 16;
    const int wrow_hi = wrow_lo + 15;

    // Q fragments: g_q is tf32-rounded; *0.125f is an exact exponent shift.
    uint32_t qa[8][4];
    const float* q0p = g_q + ((size_t)(b * SEQ + r0)) * DMODEL + h * DHEAD;
    const float* q1p = g_q + ((size_t)(b * SEQ + r1)) * DMODEL + h * DHEAD;
#pragma unroll
    for (int s = 0; s < 8; s++) {
        qa[s][0] = __float_as_uint(q0p[s * 8 + qd]     * 0.125f);
        qa[s][1] = __float_as_uint(q1p[s * 8 + qd]     * 0.125f);
        qa[s][2] = __float_as_uint(q0p[s * 8 + qd + 4] * 0.125f);
        qa[s][3] = __float_as_uint(q1p[s * 8 + qd + 4] * 0.125f);
    }

    float oacc[8][4];
#pragma unroll
    for (int i = 0; i < 8; i++)
#pragma unroll
        for (int k = 0; k < 4; k++) oacc[i][k] = 0.0f;
    float m0 = -1e30f, m1 = -1e30f, l0 = 0.0f, l1 = 0.0f;

    const int lrow = tid >> 2;            // 0..63
    const int lc   = (tid & 3) * 16;      // 0,16,32,48
    const int ntiles = 2 * qt + 2;

    // issue tile `t` into stage t&1
    auto issue_tile = [&](int t) {
        const size_t gb = ((size_t)(b * SEQ + t * 64 + lrow)) * DMODEL + h * DHEAD + lc;
        const float* kp = g_k + gb;
        const float* vp = g_v + gb;
        const uint32_t ka = sb + (uint32_t)(t & 1) * ATTN_STAGE + (uint32_t)(lrow * 68 + lc) * 4u;
        const uint32_t va = sb + (uint32_t)(t & 1) * ATTN_STAGE + 17408u + (uint32_t)(lrow * 72 + lc) * 4u;
#pragma unroll
        for (int i = 0; i < 4; i++) {
            cp16(ka + i * 16, kp + i * 4);
            cp16(va + i * 16, vp + i * 4);
        }
    };

    issue_tile(0);
    cp_commit();

    for (int kt = 0; kt < ntiles; kt++) {
        if (kt + 1 < ntiles) issue_tile(kt + 1);
        cp_commit();
        cp_wait1();          // tile kt's group complete (<=1 pending)
        __syncthreads();

        const int kbase = kt * 64;
        if (kbase <= wrow_hi) {
            const uint32_t* Ks = (const uint32_t*)(asm_s + (kt & 1) * ATTN_STAGE);
            const uint32_t* Vs = (const uint32_t*)(asm_s + (kt & 1) * ATTN_STAGE + 17408);
            const bool needmask = (kbase + 63 > wrow_lo);

            // S = Q . K^T  (16 x 64 per warp)
            float sacc[8][4];
#pragma unroll
            for (int nf = 0; nf < 8; nf++) {
                sacc[nf][0] = sacc[nf][1] = sacc[nf][2] = sacc[nf][3] = 0.0f;
#pragma unroll
                for (int s = 0; s < 8; s++) {
                    uint32_t bf[2];
                    const uint32_t* kb = &Ks[(nf * 8 + g) * 68 + s * 8 + qd];
                    bf[0] = kb[0];
                    bf[1] = kb[4];
                    mma_tf32(sacc[nf], qa[s], bf);
                }
            }

            if (needmask) {
#pragma unroll
                for (int nf = 0; nf < 8; nf++) {
                    const int c0 = kbase + nf * 8 + 2 * qd;
                    if (c0 > r0)     sacc[nf][0] = -1e30f;
                    if (c0 + 1 > r0) sacc[nf][1] = -1e30f;
                    if (c0 > r1)     sacc[nf][2] = -1e30f;
                    if (c0 + 1 > r1) sacc[nf][3] = -1e30f;
                }
            }

            // online softmax
            float mx0 = -1e30f, mx1 = -1e30f;
#pragma unroll
            for (int nf = 0; nf < 8; nf++) {
                mx0 = fmaxf(mx0, fmaxf(sacc[nf][0], sacc[nf][1]));
                mx1 = fmaxf(mx1, fmaxf(sacc[nf][2], sacc[nf][3]));
            }
            mx0 = fmaxf(mx0, __shfl_xor_sync(0xffffffffu, mx0, 1));
            mx0 = fmaxf(mx0, __shfl_xor_sync(0xffffffffu, mx0, 2));
            mx1 = fmaxf(mx1, __shfl_xor_sync(0xffffffffu, mx1, 1));
            mx1 = fmaxf(mx1, __shfl_xor_sync(0xffffffffu, mx1, 2));

            const float mn0 = fmaxf(m0, mx0), mn1 = fmaxf(m1, mx1);
            const float cr0 = __expf(m0 - mn0), cr1 = __expf(m1 - mn1);
            float sum0 = 0.0f, sum1 = 0.0f;
#pragma unroll
            for (int nf = 0; nf < 8; nf++) {
                sacc[nf][0] = __expf(sacc[nf][0] - mn0);
                sacc[nf][1] = __expf(sacc[nf][1] - mn0);
                sacc[nf][2] = __expf(sacc[nf][2] - mn1);
                sacc[nf][3] = __expf(sacc[nf][3] - mn1);
                sum0 += sacc[nf][0] + sacc[nf][1];
                sum1 += sacc[nf][2] + sacc[nf][3];
            }
            sum0 += __shfl_xor_sync(0xffffffffu, sum0, 1);
            sum0 += __shfl_xor_sync(0xffffffffu, sum0, 2);
            sum1 += __shfl_xor_sync(0xffffffffu, sum1, 1);
            sum1 += __shfl_xor_sync(0xffffffffu, sum1, 2);
            l0 = l0 * cr0 + sum0;
            l1 = l1 * cr1 + sum1;
            m0 = mn0; m1 = mn1;
#pragma unroll
            for (int nf = 0; nf < 8; nf++) {
                oacc[nf][0] *= cr0; oacc[nf][1] *= cr0;
                oacc[nf][2] *= cr1; oacc[nf][3] *= cr1;
            }

            // O += P . V with register transpose of P
            const int src0 = (lane & 0x1c) | (qd >> 1);
            const int src1 = src0 + 2;
            const bool odd = (qd & 1);
#pragma unroll
            for (int s = 0; s < 8; s++) {
                const float A0 = sacc[s][0], A1 = sacc[s][1];
                const float A2 = sacc[s][2], A3 = sacc[s][3];
                const float x0 = __shfl_sync(0xffffffffu, A0, src0);
                const float x1 = __shfl_sync(0xffffffffu, A1, src0);
                const float y0 = __shfl_sync(0xffffffffu, A2, src0);
                const float y1 = __shfl_sync(0xffffffffu, A3, src0);
                const float z0 = __shfl_sync(0xffffffffu, A0, src1);
                const float z1 = __shfl_sync(0xffffffffu, A1, src1);
                const float w0 = __shfl_sync(0xffffffffu, A2, src1);
                const float w1 = __shfl_sync(0xffffffffu, A3, src1);
                uint32_t af[4];
                af[0] = f2tf(odd ? x1 : x0);
                af[1] = f2tf(odd ? y1 : y0);
                af[2] = f2tf(odd ? z1 : z0);
                af[3] = f2tf(odd ? w1 : w0);
#pragma unroll
                for (int nf = 0; nf < 8; nf++) {
                    uint32_t bf[2];
                    const uint32_t* vb = &Vs[(s * 8 + qd) * 72 + nf * 8 + g];
                    bf[0] = vb[0];
                    bf[1] = vb[4 * 72];
                    mma_tf32(oacc[nf], af, bf);
                }
            }
        }
        __syncthreads();   // free stage kt&1 before it's refilled at kt+2
    }

    // epilogue: write O (tf32-rounded; proj consumes it as tf32 anyway)
    const float il0 = 1.0f / l0, il1 = 1.0f / l1;
    float* o0 = g_attn + ((size_t)(b * SEQ + r0)) * DMODEL + h * DHEAD;
    float* o1 = g_attn + ((size_t)(b * SEQ + r1)) * DMODEL + h * DHEAD;
#pragma unroll
    for (int nf = 0; nf < 8; nf++) {
        const int c = nf * 8 + 2 * qd;
        float2 v0, v1;
        v0.x = __uint_as_float(f2tf(oacc[nf][0] * il0));
        v0.y = __uint_as_float(f2tf(oacc[nf][1] * il0));
        v1.x = __uint_as_float(f2tf(oacc[nf][2] * il1));
        v1.y = __uint_as_float(f2tf(oacc[nf][3] * il1));
        *(float2*)&o0[c] = v0;
        *(float2*)&o1[c] = v1;
    }
}

// ---------------------------------------------------------------------------
extern "C" void kernel_launch(void* const* d_in, const int* in_sizes, int n_in,
                              void* d_out, int out_size)
{
    const float* X  = (const float*)d_in[0];
    const float* Wq = (const float*)d_in[1];
    const float* Wk = (const float*)d_in[2];
    const float* Wv = (const float*)d_in[3];
    const float* Wo = (const float*)d_in[4];
    const int*  pos = (const int*)d_in[5];

    cudaFuncSetAttribute(qkv_kernel,  cudaFuncAttributeMaxDynamicSharedMemorySize, GEMM_DSM);
    cudaFuncSetAttribute(proj_kernel, cudaFuncAttributeMaxDynamicSharedMemorySize, GEMM_DSM);
    cudaFuncSetAttribute(attn_kernel, cudaFuncAttributeMaxDynamicSharedMemorySize, ATTN_DSM);

    cvt_kernel<<<dim3(4096, 5), 256>>>(X, Wq, Wk, Wv, Wo);
    qkv_kernel<<<dim3(DMODEL / 128, BT / 128, 3), 256, GEMM_DSM>>>(pos);
    attn_kernel<<<dim3(SEQ / 128, NHEAD, BATCH), 256, ATTN_DSM>>>();
    proj_kernel<<<dim3(DMODEL / 128, BT / 128, 1), 256, GEMM_DSM>>>((float*)d_out);
}

// round 7
// speedup vs baseline: 5.9805x; 1.0447x over previous
#include <cuda_runtime.h>
#include <cuda_bf16.h>
#include <math.h>
#include <stdint.h>

#define BATCH   2
#define SEQ     2048
#define DMODEL  1024
#define NHEAD   16
#define DHEAD   64
#define BT      (BATCH * SEQ)
#define NQT     (SEQ / 128)     // 16 q-tiles of 128

// Scratch (device globals). All hold tf32-rounded fp32.
__device__ float g_q[BT * DMODEL];
__device__ float g_k[BT * DMODEL];
__device__ float g_v[BT * DMODEL];
__device__ float g_attn[BT * DMODEL];
__device__ float g_xc[BT * DMODEL];
__device__ float g_w4[4 * DMODEL * DMODEL];

__device__ __forceinline__ uint32_t f2tf(float f) {
    uint32_t u;
    asm("cvt.rna.tf32.f32 %0, %1;" : "=r"(u) : "f"(f));
    return u;
}

__device__ __forceinline__ uint32_t smem_u32(const void* p) {
    uint32_t a;
    asm("{ .reg .u64 t; cvta.to.shared.u64 t, %1; cvt.u32.u64 %0, t; }" : "=r"(a) : "l"(p));
    return a;
}

__device__ __forceinline__ void mma_tf32(float c[4], const uint32_t a[4], const uint32_t b[2]) {
    asm volatile(
        "mma.sync.aligned.m16n8k8.row.col.f32.tf32.tf32.f32 "
        "{%0,%1,%2,%3}, {%4,%5,%6,%7}, {%8,%9}, {%0,%1,%2,%3};"
        : "+f"(c[0]), "+f"(c[1]), "+f"(c[2]), "+f"(c[3])
        : "r"(a[0]), "r"(a[1]), "r"(a[2]), "r"(a[3]), "r"(b[0]), "r"(b[1]));
}

__device__ __forceinline__ void cp16(uint32_t dst, const void* src) {
    asm volatile("cp.async.cg.shared.global [%0], [%1], 16;" :: "r"(dst), "l"(src));
}
__device__ __forceinline__ void cp_commit() {
    asm volatile("cp.async.commit_group;");
}
__device__ __forceinline__ void cp_wait1() {
    asm volatile("cp.async.wait_group 1;");
}

// ---------------------------------------------------------------------------
// Prepass: round X and the four weights to tf32 once.
// ---------------------------------------------------------------------------
__global__ void cvt_kernel(const float* __restrict__ X,
                           const float* __restrict__ Wq,
                           const float* __restrict__ Wk,
                           const float* __restrict__ Wv,
                           const float* __restrict__ Wo)
{
    const int y = blockIdx.y;
    const float* src;
    float* dst;
    int n;
    if (y == 0)      { src = X;  dst = g_xc;                          n = BT * DMODEL; }
    else             { src = (y == 1) ? Wq : (y == 2) ? Wk : (y == 3) ? Wv : Wo;
                       dst = g_w4 + (size_t)(y - 1) * DMODEL * DMODEL; n = DMODEL * DMODEL; }
    const int i = (blockIdx.x * 256 + threadIdx.x) * 4;
    if (i < n) {
        float4 v = *(const float4*)(src + i);
        uint4 u;
        u.x = f2tf(v.x); u.y = f2tf(v.y); u.z = f2tf(v.z); u.w = f2tf(v.w);
        *(uint4*)(dst + i) = u;
    }
}

// ---------------------------------------------------------------------------
// TF32 tensor-core GEMM: C[m,n] = sum_k A[m,k]*B[n,k]; inputs pre-tf32.
// Block 128x128, 8 warps (2x4), warp tile 64x32.
// K-stage 32, 3-stage cp.async pipeline, ONE __syncthreads per 32-k step.
// Smem row stride 36 words: bank = 4*row + k -> conflict-free frag LDS.
// ---------------------------------------------------------------------------
#define GSTG_B   36864u                 // bytes per stage (A 18432 + B 18432)
#define GEMM_DSM (3 * 36864)            // 110592

__device__ __forceinline__ void gemm_tc(const float* __restrict__ A,
                                        const float* __restrict__ B,
                                        float* __restrict__ C,
                                        int rope, const int* __restrict__ pos,
                                        int tfout)
{
    extern __shared__ float dsm[];
    const uint32_t sb = smem_u32(dsm);

    const int tid  = threadIdx.x;
    const int warp = tid >> 5, lane = tid & 31;
    const int wm = warp >> 2, wn = warp & 3;
    const int g  = lane >> 2, qd = lane & 3;
    const int mbase = blockIdx.y * 128;
    const int nbase = blockIdx.x * 128;

    // producer: row = tid>>1 (0..127), half kk = (tid&1)*16; 4 chunks each mat
    const int r  = tid >> 1;
    const int kk = (tid & 1) * 16;
    const float* Arow = A + (size_t)(mbase + r) * DMODEL + kk;
    const float* Brow = B + (size_t)(nbase + r) * DMODEL + kk;
    const uint32_t dOff = (uint32_t)r * 144u + (uint32_t)kk * 4u;

    float acc[4][4][4];
#pragma unroll
    for (int i = 0; i < 4; i++)
#pragma unroll
        for (int j = 0; j < 4; j++)
#pragma unroll
            for (int k = 0; k < 4; k++) acc[i][j][k] = 0.0f;

    // prologue: stages 0,1
#pragma unroll
    for (int s = 0; s < 2; s++) {
        const uint32_t da = sb + (uint32_t)s * GSTG_B + dOff;
        const uint32_t db = da + 18432u;
#pragma unroll
        for (int c = 0; c < 4; c++) {
            cp16(da + c * 16, Arow + s * 32 + c * 4);
            cp16(db + c * 16, Brow + s * 32 + c * 4);
        }
        cp_commit();
    }

    const int NK = DMODEL / 32;   // 32 iterations
    for (int kt = 0; kt < NK; kt++) {
        cp_wait1();
        __syncthreads();

        if (kt + 2 < NK) {
            const int s = kt + 2;
            const uint32_t da = sb + (uint32_t)(s % 3) * GSTG_B + dOff;
            const uint32_t db = da + 18432u;
#pragma unroll
            for (int c = 0; c < 4; c++) {
                cp16(da + c * 16, Arow + s * 32 + c * 4);
                cp16(db + c * 16, Brow + s * 32 + c * 4);
            }
        }
        cp_commit();

        const uint32_t* Ast = (const uint32_t*)(dsm + (kt % 3) * 9216);
        const uint32_t* Bst = (const uint32_t*)(dsm + (kt % 3) * 9216 + 4608);
#pragma unroll
        for (int ks = 0; ks < 4; ks++) {
            uint32_t af[4][4], bf[4][2];
#pragma unroll
            for (int mf = 0; mf < 4; mf++) {
                const uint32_t* p = &Ast[(wm * 64 + mf * 16 + g) * 36 + ks * 8 + qd];
                af[mf][0] = p[0];
                af[mf][1] = p[288];     // +8 rows
                af[mf][2] = p[4];
                af[mf][3] = p[292];
            }
#pragma unroll
            for (int nf = 0; nf < 4; nf++) {
                const uint32_t* p = &Bst[(wn * 32 + nf * 8 + g) * 36 + ks * 8 + qd];
                bf[nf][0] = p[0];
                bf[nf][1] = p[4];
            }
#pragma unroll
            for (int mf = 0; mf < 4; mf++)
#pragma unroll
                for (int nf = 0; nf < 4; nf++)
                    mma_tf32(acc[mf][nf], af[mf], bf[nf]);
        }
    }

    // epilogue (optional fused RoPE; optional tf32 rounding of stores)
#pragma unroll
    for (int mf = 0; mf < 4; mf++) {
        const int r0 = mbase + wm * 64 + mf * 16 + g;
        const int r1 = r0 + 8;
        float p0 = 0.0f, p1 = 0.0f;
        if (rope) {
            p0 = (float)pos[r0 & (SEQ - 1)];
            p1 = (float)pos[r1 & (SEQ - 1)];
        }
#pragma unroll
        for (int nf = 0; nf < 4; nf++) {
            const int col = nbase + wn * 32 + nf * 8 + 2 * qd;
            float a0 = acc[mf][nf][0], a1 = acc[mf][nf][1];
            float a2 = acc[mf][nf][2], a3 = acc[mf][nf][3];
            if (rope) {
                const int j = (col >> 1) & 31;
                const float inv = exp2f((float)j * -0.41524101186092029f);
                float s0, c0, s1, c1;
                sincosf(p0 * inv, &s0, &c0);
                sincosf(p1 * inv, &s1, &c1);
                float n0 = a0 * c0 - a1 * s0;
                float n1 = a0 * s0 + a1 * c0;
                float n2 = a2 * c1 - a3 * s1;
                float n3 = a2 * s1 + a3 * c1;
                a0 = n0; a1 = n1; a2 = n2; a3 = n3;
            }
            if (tfout) {
                a0 = __uint_as_float(f2tf(a0));
                a1 = __uint_as_float(f2tf(a1));
                a2 = __uint_as_float(f2tf(a2));
                a3 = __uint_as_float(f2tf(a3));
            }
            *(float2*)&C[(size_t)r0 * DMODEL + col] = make_float2(a0, a1);
            *(float2*)&C[(size_t)r1 * DMODEL + col] = make_float2(a2, a3);
        }
    }
}

__global__ void __launch_bounds__(256, 2) qkv_kernel(const int* __restrict__ pos)
{
    const int z = blockIdx.z;
    const float* W = g_w4 + (size_t)z * DMODEL * DMODEL;
    float* dst = (z == 0) ? g_q : (z == 1) ? g_k : g_v;
    gemm_tc(g_xc, W, dst, z < 2 ? 1 : 0, pos, 1);
}

__global__ void __launch_bounds__(256, 2) proj_kernel(float* __restrict__ out)
{
    gemm_tc(g_attn, g_w4 + (size_t)3 * DMODEL * DMODEL, out, 0, (const int*)0, 0);
}

// ---------------------------------------------------------------------------
// Causal flash attention, tf32 warp MMA, cp.async double-buffered K/V tiles.
// 256 threads / 128 queries per q-tile (8 warps x 16 q-rows), key tiles of 64.
// Each CTA processes the q-tile PAIR (p, NQT-1-p): uniform 34 work units.
// ---------------------------------------------------------------------------
#define ATTN_STAGE 35840
#define ATTN_DSM   (2 * ATTN_STAGE)

__device__ __forceinline__ void attn_qtile(int qt, int b, int h,
                                           char* asm_s, uint32_t sb)
{
    const int tid = threadIdx.x, warp = tid >> 5, lane = tid & 31;
    const int g = lane >> 2, qd = lane & 3;

    const int r0 = qt * 128 + warp * 16 + g;
    const int r1 = r0 + 8;
    const int wrow_lo = qt * 128 + warp * 16;
    const int wrow_hi = wrow_lo + 15;

    uint32_t qa[8][4];
    const float* q0p = g_q + ((size_t)(b * SEQ + r0)) * DMODEL + h * DHEAD;
    const float* q1p = g_q + ((size_t)(b * SEQ + r1)) * DMODEL + h * DHEAD;
#pragma unroll
    for (int s = 0; s < 8; s++) {
        qa[s][0] = __float_as_uint(q0p[s * 8 + qd]     * 0.125f);
        qa[s][1] = __float_as_uint(q1p[s * 8 + qd]     * 0.125f);
        qa[s][2] = __float_as_uint(q0p[s * 8 + qd + 4] * 0.125f);
        qa[s][3] = __float_as_uint(q1p[s * 8 + qd + 4] * 0.125f);
    }

    float oacc[8][4];
#pragma unroll
    for (int i = 0; i < 8; i++)
#pragma unroll
        for (int k = 0; k < 4; k++) oacc[i][k] = 0.0f;
    float m0 = -1e30f, m1 = -1e30f, l0 = 0.0f, l1 = 0.0f;

    const int lrow = tid >> 2;
    const int lc   = (tid & 3) * 16;
    const int ntiles = 2 * qt + 2;

    // issue K/V tile t into stage t&1
    const size_t gstep = (size_t)(b * SEQ + lrow) * DMODEL + h * DHEAD + lc;
    for (int t = 0; t < 1; t++) {   // tile 0
        const float* kp = g_k + gstep;
        const float* vp = g_v + gstep;
        const uint32_t ka = sb + (uint32_t)(lrow * 68 + lc) * 4u;
        const uint32_t va = sb + 17408u + (uint32_t)(lrow * 72 + lc) * 4u;
#pragma unroll
        for (int i = 0; i < 4; i++) {
            cp16(ka + i * 16, kp + i * 4);
            cp16(va + i * 16, vp + i * 4);
        }
    }
    cp_commit();

    for (int kt = 0; kt < ntiles; kt++) {
        if (kt + 1 < ntiles) {
            const int t = kt + 1;
            const float* kp = g_k + gstep + (size_t)t * 64 * DMODEL;
            const float* vp = g_v + gstep + (size_t)t * 64 * DMODEL;
            const uint32_t ka = sb + (uint32_t)(t & 1) * ATTN_STAGE + (uint32_t)(lrow * 68 + lc) * 4u;
            const uint32_t va = sb + (uint32_t)(t & 1) * ATTN_STAGE + 17408u + (uint32_t)(lrow * 72 + lc) * 4u;
#pragma unroll
            for (int i = 0; i < 4; i++) {
                cp16(ka + i * 16, kp + i * 4);
                cp16(va + i * 16, vp + i * 4);
            }
        }
        cp_commit();
        cp_wait1();
        __syncthreads();

        const int kbase = kt * 64;
        if (kbase <= wrow_hi) {
            const uint32_t* Ks = (const uint32_t*)(asm_s + (kt & 1) * ATTN_STAGE);
            const uint32_t* Vs = (const uint32_t*)(asm_s + (kt & 1) * ATTN_STAGE + 17408);
            const bool needmask = (kbase + 63 > wrow_lo);

            float sacc[8][4];
#pragma unroll
            for (int nf = 0; nf < 8; nf++) {
                sacc[nf][0] = sacc[nf][1] = sacc[nf][2] = sacc[nf][3] = 0.0f;
#pragma unroll
                for (int s = 0; s < 8; s++) {
                    uint32_t bf[2];
                    const uint32_t* kb = &Ks[(nf * 8 + g) * 68 + s * 8 + qd];
                    bf[0] = kb[0];
                    bf[1] = kb[4];
                    mma_tf32(sacc[nf], qa[s], bf);
                }
            }

            if (needmask) {
#pragma unroll
                for (int nf = 0; nf < 8; nf++) {
                    const int c0 = kbase + nf * 8 + 2 * qd;
                    if (c0 > r0)     sacc[nf][0] = -1e30f;
                    if (c0 + 1 > r0) sacc[nf][1] = -1e30f;
                    if (c0 > r1)     sacc[nf][2] = -1e30f;
                    if (c0 + 1 > r1) sacc[nf][3] = -1e30f;
                }
            }

            float mx0 = -1e30f, mx1 = -1e30f;
#pragma unroll
            for (int nf = 0; nf < 8; nf++) {
                mx0 = fmaxf(mx0, fmaxf(sacc[nf][0], sacc[nf][1]));
                mx1 = fmaxf(mx1, fmaxf(sacc[nf][2], sacc[nf][3]));
            }
            mx0 = fmaxf(mx0, __shfl_xor_sync(0xffffffffu, mx0, 1));
            mx0 = fmaxf(mx0, __shfl_xor_sync(0xffffffffu, mx0, 2));
            mx1 = fmaxf(mx1, __shfl_xor_sync(0xffffffffu, mx1, 1));
            mx1 = fmaxf(mx1, __shfl_xor_sync(0xffffffffu, mx1, 2));

            const float mn0 = fmaxf(m0, mx0), mn1 = fmaxf(m1, mx1);
            const float cr0 = __expf(m0 - mn0), cr1 = __expf(m1 - mn1);
            float sum0 = 0.0f, sum1 = 0.0f;
#pragma unroll
            for (int nf = 0; nf < 8; nf++) {
                sacc[nf][0] = __expf(sacc[nf][0] - mn0);
                sacc[nf][1] = __expf(sacc[nf][1] - mn0);
                sacc[nf][2] = __expf(sacc[nf][2] - mn1);
                sacc[nf][3] = __expf(sacc[nf][3] - mn1);
                sum0 += sacc[nf][0] + sacc[nf][1];
                sum1 += sacc[nf][2] + sacc[nf][3];
            }
            sum0 += __shfl_xor_sync(0xffffffffu, sum0, 1);
            sum0 += __shfl_xor_sync(0xffffffffu, sum0, 2);
            sum1 += __shfl_xor_sync(0xffffffffu, sum1, 1);
            sum1 += __shfl_xor_sync(0xffffffffu, sum1, 2);
            l0 = l0 * cr0 + sum0;
            l1 = l1 * cr1 + sum1;
            m0 = mn0; m1 = mn1;
#pragma unroll
            for (int nf = 0; nf < 8; nf++) {
                oacc[nf][0] *= cr0; oacc[nf][1] *= cr0;
                oacc[nf][2] *= cr1; oacc[nf][3] *= cr1;
            }

            const int src0 = (lane & 0x1c) | (qd >> 1);
            const int src1 = src0 + 2;
            const bool odd = (qd & 1);
#pragma unroll
            for (int s = 0; s < 8; s++) {
                const float A0 = sacc[s][0], A1 = sacc[s][1];
                const float A2 = sacc[s][2], A3 = sacc[s][3];
                const float x0 = __shfl_sync(0xffffffffu, A0, src0);
                const float x1 = __shfl_sync(0xffffffffu, A1, src0);
                const float y0 = __shfl_sync(0xffffffffu, A2, src0);
                const float y1 = __shfl_sync(0xffffffffu, A3, src0);
                const float z0 = __shfl_sync(0xffffffffu, A0, src1);
                const float z1 = __shfl_sync(0xffffffffu, A1, src1);
                const float w0 = __shfl_sync(0xffffffffu, A2, src1);
                const float w1 = __shfl_sync(0xffffffffu, A3, src1);
                uint32_t af[4];
                af[0] = f2tf(odd ? x1 : x0);
                af[1] = f2tf(odd ? y1 : y0);
                af[2] = f2tf(odd ? z1 : z0);
                af[3] = f2tf(odd ? w1 : w0);
#pragma unroll
                for (int nf = 0; nf < 8; nf++) {
                    uint32_t bf[2];
                    const uint32_t* vb = &Vs[(s * 8 + qd) * 72 + nf * 8 + g];
                    bf[0] = vb[0];
                    bf[1] = vb[4 * 72];
                    mma_tf32(oacc[nf], af, bf);
                }
            }
        }
        __syncthreads();
    }

    const float il0 = 1.0f / l0, il1 = 1.0f / l1;
    float* o0 = g_attn + ((size_t)(b * SEQ + r0)) * DMODEL + h * DHEAD;
    float* o1 = g_attn + ((size_t)(b * SEQ + r1)) * DMODEL + h * DHEAD;
#pragma unroll
    for (int nf = 0; nf < 8; nf++) {
        const int c = nf * 8 + 2 * qd;
        float2 v0, v1;
        v0.x = __uint_as_float(f2tf(oacc[nf][0] * il0));
        v0.y = __uint_as_float(f2tf(oacc[nf][1] * il0));
        v1.x = __uint_as_float(f2tf(oacc[nf][2] * il1));
        v1.y = __uint_as_float(f2tf(oacc[nf][3] * il1));
        *(float2*)&o0[c] = v0;
        *(float2*)&o1[c] = v1;
    }
}

__global__ void __launch_bounds__(256) attn_kernel()
{
    extern __shared__ char asm_s[];
    const uint32_t sb = smem_u32(asm_s);
    const int b = blockIdx.z, h = blockIdx.y;

    // paired q-tiles: (NQT-1-p) heavy + p light = uniform 34 units/CTA
    attn_qtile(NQT - 1 - blockIdx.x, b, h, asm_s, sb);
    __syncthreads();
    attn_qtile(blockIdx.x, b, h, asm_s, sb);
}

// ---------------------------------------------------------------------------
extern "C" void kernel_launch(void* const* d_in, const int* in_sizes, int n_in,
                              void* d_out, int out_size)
{
    const float* X  = (const float*)d_in[0];
    const float* Wq = (const float*)d_in[1];
    const float* Wk = (const float*)d_in[2];
    const float* Wv = (const float*)d_in[3];
    const float* Wo = (const float*)d_in[4];
    const int*  pos = (const int*)d_in[5];

    cudaFuncSetAttribute(qkv_kernel,  cudaFuncAttributeMaxDynamicSharedMemorySize, GEMM_DSM);
    cudaFuncSetAttribute(proj_kernel, cudaFuncAttributeMaxDynamicSharedMemorySize, GEMM_DSM);
    cudaFuncSetAttribute(attn_kernel, cudaFuncAttributeMaxDynamicSharedMemorySize, ATTN_DSM);

    cvt_kernel<<<dim3(4096, 5), 256>>>(X, Wq, Wk, Wv, Wo);
    qkv_kernel<<<dim3(DMODEL / 128, BT / 128, 3), 256, GEMM_DSM>>>(pos);
    attn_kernel<<<dim3(NQT / 2, NHEAD, BATCH), 256, ATTN_DSM>>>();
    proj_kernel<<<dim3(DMODEL / 128, BT / 128, 1), 256, GEMM_DSM>>>((float*)d_out);
}